// round 14
// baseline (speedup 1.0000x reference)
#include <cuda_runtime.h>
#include <cuda_bf16.h>
#include <math.h>
#include <mma.h>

using namespace nvcuda;

#define D   128
#define CH  7
#define NC  8
#define NS  4
#define MAXM  40000
#define MP    (MAXM + 128)
#define MAXET 680000
#define WLMAX  8192
#define WL2MAX 32768

// ---------------- scratch (static device globals; no allocation) -------------
__device__ int   g_count[MAXM + 1];
__device__ int   g_off[MAXM + 1];
__device__ int   g_cursor[MAXM];
__device__ int   g_csr[MAXET];
__device__ int   g_wl[WLMAX];
__device__ int   g_wlcount;
__device__ int   g_wl2[WL2MAX];
__device__ int   g_wl2count;
__device__ float g_xlA[(size_t)MP * D];   // actor layer-1 projections (2-hop rows only)
__device__ float g_xrA[(size_t)MP * D];
__device__ float g_xlC[(size_t)MP * D];   // critic layer-1 projections (dense)
__device__ float g_xrC[(size_t)MP * D];
__device__ float g_yl [(size_t)MP * D];   // critic layer-2 projections (dense)
__device__ float g_yr [(size_t)MP * D];
__device__ float g_hA [(size_t)MP * D];
__device__ float g_hC [(size_t)MP * D];
__device__ float g_lg[64 * CH];

// ---------------- CSR build --------------------------------------------------
__global__ void k_hist(const int* __restrict__ tgt, int E, int M) {
    int stride = gridDim.x * blockDim.x;
    int ET = E + M;
    for (int i = blockIdx.x * blockDim.x + threadIdx.x; i < ET; i += stride) {
        int t = (i < E) ? tgt[i] : (i - E);
        atomicAdd(&g_count[t], 1);
    }
}

__global__ void k_scan(int M) {  // single block, 1024 threads
    __shared__ int sh[1024];
    int tid = threadIdx.x;
    int chunk = (M + 1023) >> 10;
    int beg = tid * chunk;
    int end = min(beg + chunk, M);
    int s = 0;
    for (int i = beg; i < end; i++) s += g_count[i];
    sh[tid] = s;
    __syncthreads();
    for (int o = 1; o < 1024; o <<= 1) {
        int v = (tid >= o) ? sh[tid - o] : 0;
        __syncthreads();
        sh[tid] += v;
        __syncthreads();
    }
    int run = sh[tid] - s;
    for (int i = beg; i < end; i++) {
        g_off[i] = run;
        g_cursor[i] = run;
        run += g_count[i];
    }
    if (tid == 1023) g_off[M] = sh[1023];
}

__global__ void k_scatter(const int* __restrict__ src, const int* __restrict__ tgt,
                          int E, int M) {
    int stride = gridDim.x * blockDim.x;
    int ET = E + M;
    for (int i = blockIdx.x * blockDim.x + threadIdx.x; i < ET; i += stride) {
        int t, s;
        if (i < E) { t = tgt[i]; s = src[i]; }
        else       { t = i - E;  s = i - E; }
        int pos = atomicAdd(&g_cursor[t], 1);
        g_csr[pos] = s;
    }
}

// warp-per-node segment sort over rows [w0, wEnd)
__global__ void k_sortwarp(int w0, int wEnd) {
    int w = w0 + ((blockIdx.x * blockDim.x + threadIdx.x) >> 5);
    if (w >= wEnd) return;
    int lane = threadIdx.x & 31;
    int beg = g_off[w], end = g_off[w + 1];
    int deg = end - beg;
    if (deg <= 1) return;
    if (deg <= 32) {
        int v = (lane < deg) ? g_csr[beg + lane] : 0x7fffffff;
        #pragma unroll
        for (int k = 2; k <= 32; k <<= 1) {
            #pragma unroll
            for (int j = k >> 1; j > 0; j >>= 1) {
                int partner = __shfl_xor_sync(0xffffffffu, v, j);
                bool dir   = ((lane & k) == 0);
                bool lower = ((lane & j) == 0);
                v = (lower == dir) ? min(v, partner) : max(v, partner);
            }
        }
        if (lane < deg) g_csr[beg + lane] = v;
    } else if (lane == 0) {
        for (int i = beg + 1; i < end; i++) {
            int v = g_csr[i]; int j = i - 1;
            while (j >= beg && g_csr[j] > v) { g_csr[j + 1] = g_csr[j]; j--; }
            g_csr[j + 1] = v;
        }
    }
}

// ---------------- actor worklists --------------------------------------------
// wl  = 32 targets + their sources (nodes whose gat output is needed)
__global__ void k_mkwl(int B, int N) {
    int t = threadIdx.x >> 5;     // one block, 1024 threads
    int lane = threadIdx.x & 31;
    if (t >= B * NC) return;
    int row = (t >> 3) * N + (t & 7);
    int beg = g_off[row], end = g_off[row + 1];
    int deg = end - beg;
    int pos = 0;
    if (lane == 0) pos = atomicAdd(&g_wlcount, deg + 1);
    pos = __shfl_sync(0xffffffffu, pos, 0);
    for (int i = lane; i < deg + 1; i += 32) {
        int idx = pos + i;
        if (idx < WLMAX)
            g_wl[idx] = (i == 0) ? row : g_csr[beg + i - 1];
    }
}

// wl2 = union of CSR segments of wl nodes (2-hop; includes wl via self-loops).
// Rows whose projections are needed. Duplicates benign (idempotent writes).
__global__ void k_mkwl2() {
    int wi = (blockIdx.x * blockDim.x + threadIdx.x) >> 5;
    int lane = threadIdx.x & 31;
    int n = g_wlcount; if (n > WLMAX) n = WLMAX;
    if (wi >= n) return;
    int row = g_wl[wi];
    int beg = g_off[row], end = g_off[row + 1];
    int deg = end - beg;
    int pos = 0;
    if (lane == 0) pos = atomicAdd(&g_wl2count, deg);
    pos = __shfl_sync(0xffffffffu, pos, 0);
    for (int i = lane; i < deg; i += 32) {
        int idx = pos + i;
        if (idx < WL2MAX) g_wl2[idx] = g_csr[beg + i];
    }
}

// fp32 projection of wl2 nodes only: xl[row]=x[row]@Wl, xr[row]=x[row]@Wr
__global__ void k_projwl(const float* __restrict__ x,
                         const float* __restrict__ Wl, const float* __restrict__ Wr,
                         float* __restrict__ xl, float* __restrict__ xr) {
    __shared__ float xs[D];
    int n = g_wl2count; if (n > WL2MAX) n = WL2MAX;
    for (int i = blockIdx.x; i < n; i += gridDim.x) {
        int row = g_wl2[i];
        for (int k = threadIdx.x; k < D; k += blockDim.x)
            xs[k] = x[(size_t)row * D + k];
        __syncthreads();
        int c = threadIdx.x & 127;
        const float* W = (threadIdx.x < 128) ? Wl : Wr;
        float* o       = (threadIdx.x < 128) ? xl : xr;
        float s = 0.f;
        #pragma unroll 8
        for (int k = 0; k < D; k++) s = fmaf(xs[k], W[k * D + c], s);
        o[(size_t)row * D + c] = s;
        __syncthreads();
    }
}

// ---------------- bf16x3 tensor-core dual GEMM (no bias, direct store) -------
#define LDB 136

__device__ __forceinline__ void split_store4(float4 v, __nv_bfloat16* hi,
                                             __nv_bfloat16* lo, int idx) {
    __nv_bfloat16 h0 = __float2bfloat16(v.x), h1 = __float2bfloat16(v.y),
                  h2 = __float2bfloat16(v.z), h3 = __float2bfloat16(v.w);
    float l0 = v.x - __bfloat162float(h0), l1 = v.y - __bfloat162float(h1),
          l2 = v.z - __bfloat162float(h2), l3 = v.w - __bfloat162float(h3);
    __nv_bfloat162 hp0 = __halves2bfloat162(h0, h1), hp1 = __halves2bfloat162(h2, h3);
    uint2 hv; hv.x = *(unsigned*)&hp0; hv.y = *(unsigned*)&hp1;
    *(uint2*)&hi[idx] = hv;
    __nv_bfloat162 lp0 = __floats2bfloat162_rn(l0, l1), lp1 = __floats2bfloat162_rn(l2, l3);
    uint2 lv; lv.x = *(unsigned*)&lp0; lv.y = *(unsigned*)&lp1;
    *(uint2*)&lo[idx] = lv;
}

__global__ void k_gemmN(const float* __restrict__ A,
                        const float* __restrict__ W0, float* __restrict__ C0,
                        const float* __restrict__ W1, float* __restrict__ C1,
                        int M) {
    extern __shared__ char smraw[];
    __nv_bfloat16* Ahi = (__nv_bfloat16*)smraw;
    __nv_bfloat16* Alo = Ahi + 128 * LDB;
    __nv_bfloat16* Whi = Alo + 128 * LDB;
    __nv_bfloat16* Wlo = Whi + 128 * LDB;

    int tid = threadIdx.x;       // 256
    int row0 = blockIdx.x * 128;
    int r = tid >> 1, half = tid & 1;
    int cbase = half * 64;

    const float* Wt[2] = {W0, W1};
    float*       Ct[2] = {C0, C1};

    {
        int row = row0 + r;
        const float* ap = A + (size_t)row * D + cbase;
        #pragma unroll
        for (int q = 0; q < 16; q++) {
            float4 v = (row < M) ? *(const float4*)(ap + q * 4)
                                 : make_float4(0.f, 0.f, 0.f, 0.f);
            split_store4(v, Ahi, Alo, r * LDB + cbase + q * 4);
        }
    }

    int w  = tid >> 5;
    int wr = w >> 2, wc = w & 3;   // warp tile: 64 rows x 32 cols

    for (int pass = 0; pass < 2; pass++) {
        const float* W = Wt[pass];
        float* C       = Ct[pass];

        if (pass > 0) __syncthreads();
        {
            const float* wp = W + r * D + cbase;
            #pragma unroll
            for (int q = 0; q < 16; q++)
                split_store4(*(const float4*)(wp + q * 4), Whi, Wlo,
                             r * LDB + cbase + q * 4);
        }
        __syncthreads();

        wmma::fragment<wmma::accumulator, 16, 16, 16, float> acc[4][2];
        #pragma unroll
        for (int m = 0; m < 4; m++)
            #pragma unroll
            for (int n = 0; n < 2; n++) wmma::fill_fragment(acc[m][n], 0.f);

        wmma::fragment<wmma::matrix_a, 16, 16, 16, __nv_bfloat16, wmma::row_major> ah[4], al[4];
        wmma::fragment<wmma::matrix_b, 16, 16, 16, __nv_bfloat16, wmma::row_major> bh[2], bl[2];

        #pragma unroll
        for (int kk = 0; kk < 8; kk++) {
            int k0 = kk * 16;
            #pragma unroll
            for (int n = 0; n < 2; n++) {
                wmma::load_matrix_sync(bh[n], &Whi[k0 * LDB + wc * 32 + n * 16], LDB);
                wmma::load_matrix_sync(bl[n], &Wlo[k0 * LDB + wc * 32 + n * 16], LDB);
            }
            #pragma unroll
            for (int m = 0; m < 4; m++) {
                wmma::load_matrix_sync(ah[m], &Ahi[(wr * 64 + m * 16) * LDB + k0], LDB);
                wmma::load_matrix_sync(al[m], &Alo[(wr * 64 + m * 16) * LDB + k0], LDB);
            }
            #pragma unroll
            for (int m = 0; m < 4; m++)
                #pragma unroll
                for (int n = 0; n < 2; n++) {
                    wmma::mma_sync(acc[m][n], ah[m], bl[n], acc[m][n]);
                    wmma::mma_sync(acc[m][n], al[m], bh[n], acc[m][n]);
                    wmma::mma_sync(acc[m][n], ah[m], bh[n], acc[m][n]);
                }
        }

        #pragma unroll
        for (int m = 0; m < 4; m++)
            #pragma unroll
            for (int n = 0; n < 2; n++)
                wmma::store_matrix_sync(
                    C + (size_t)(row0 + wr * 64 + m * 16) * D + wc * 32 + n * 16,
                    acc[m][n], D, wmma::mem_row_major);
    }
}

// ---------------- GATv2 node body (bias-folded, prefetch) --------------------
__device__ __forceinline__ void gat_node(
    int w, int lane,
    const float* __restrict__ ul, const float* __restrict__ ur,
    const float* __restrict__ att, const float* __restrict__ bl,
    const float* __restrict__ br, const float* __restrict__ bo,
    float* __restrict__ out, float slope) {
    float4 bl4 = *(const float4*)(bl + lane * 4);
    float4 xr4 = *(const float4*)(ur + (size_t)w * D + lane * 4);
    {
        float4 br4 = *(const float4*)(br + lane * 4);
        xr4.x += bl4.x + br4.x; xr4.y += bl4.y + br4.y;
        xr4.z += bl4.z + br4.z; xr4.w += bl4.w + br4.w;
    }
    float4 at4 = *(const float4*)(att + lane * 4);
    int beg = g_off[w], end = g_off[w + 1];

    float m = -INFINITY, d = 0.f;
    float4 acc = make_float4(0.f, 0.f, 0.f, 0.f);

    float4 aCur = *(const float4*)(ul + (size_t)g_csr[beg] * D + lane * 4);
    int sNext = (beg + 1 < end) ? g_csr[beg + 1] : 0;

    for (int e = beg; e < end; e++) {
        float4 a = aCur;
        if (e + 1 < end) {
            aCur = *(const float4*)(ul + (size_t)sNext * D + lane * 4);
            if (e + 2 < end) sNext = g_csr[e + 2];
        }
        float t0 = a.x + xr4.x; t0 = (t0 > 0.f) ? t0 : 0.2f * t0;
        float t1 = a.y + xr4.y; t1 = (t1 > 0.f) ? t1 : 0.2f * t1;
        float t2 = a.z + xr4.z; t2 = (t2 > 0.f) ? t2 : 0.2f * t2;
        float t3 = a.w + xr4.w; t3 = (t3 > 0.f) ? t3 : 0.2f * t3;
        float p = t0 * at4.x + t1 * at4.y + t2 * at4.z + t3 * at4.w;
        #pragma unroll
        for (int o = 16; o; o >>= 1) p += __shfl_xor_sync(0xffffffffu, p, o);

        if (p <= m) {
            float wgt = __expf(p - m);
            d += wgt;
            acc.x += wgt * a.x; acc.y += wgt * a.y;
            acc.z += wgt * a.z; acc.w += wgt * a.w;
        } else {
            float c1 = __expf(m - p);
            d = d * c1 + 1.f;
            acc.x = acc.x * c1 + a.x; acc.y = acc.y * c1 + a.y;
            acc.z = acc.z * c1 + a.z; acc.w = acc.w * c1 + a.w;
            m = p;
        }
    }

    float inv = 1.f / (d + 1e-16f);
    float4 bo4 = *(const float4*)(bo + lane * 4);
    float o0 = acc.x * inv + bl4.x + bo4.x;
    float o1 = acc.y * inv + bl4.y + bo4.y;
    float o2 = acc.z * inv + bl4.z + bo4.z;
    float o3 = acc.w * inv + bl4.w + bo4.w;
    o0 = (o0 > 0.f) ? o0 : slope * o0;
    o1 = (o1 > 0.f) ? o1 : slope * o1;
    o2 = (o2 > 0.f) ? o2 : slope * o2;
    o3 = (o3 > 0.f) ? o3 : slope * o3;
    *(float4*)(out + (size_t)w * D + lane * 4) = make_float4(o0, o1, o2, o3);
}

__global__ void k_gat1(
    const float* __restrict__ ul, const float* __restrict__ ur,
    const float* __restrict__ att, const float* __restrict__ bl,
    const float* __restrict__ br, const float* __restrict__ bo,
    float* __restrict__ out, int w0, int wEnd, float slope) {
    int w = w0 + ((blockIdx.x * blockDim.x + threadIdx.x) >> 5);
    if (w >= wEnd) return;
    gat_node(w, threadIdx.x & 31, ul, ur, att, bl, br, bo, out, slope);
}

__global__ void k_gat1wl(
    const float* __restrict__ ul, const float* __restrict__ ur,
    const float* __restrict__ att, const float* __restrict__ bl,
    const float* __restrict__ br, const float* __restrict__ bo,
    float* __restrict__ out, float slope) {
    int idx = (blockIdx.x * blockDim.x + threadIdx.x) >> 5;
    int n = g_wlcount; if (n > WLMAX) n = WLMAX;
    if (idx >= n) return;
    gat_node(g_wl[idx], threadIdx.x & 31, ul, ur, att, bl, br, bo, out, slope);
}

// ---------------- c2 GATv2 + fused value head --------------------------------
__global__ void k_gatV(
    const float* __restrict__ ul, const float* __restrict__ ur,
    const float* __restrict__ att, const float* __restrict__ bl,
    const float* __restrict__ br, const float* __restrict__ bo,
    const float* __restrict__ fcW, const float* __restrict__ fcb,
    float* __restrict__ value, int M) {
    int w = (blockIdx.x * blockDim.x + threadIdx.x) >> 5;
    if (w >= M) return;
    int lane = threadIdx.x & 31;

    float4 bl4 = *(const float4*)(bl + lane * 4);
    float4 xr4 = *(const float4*)(ur + (size_t)w * D + lane * 4);
    {
        float4 br4 = *(const float4*)(br + lane * 4);
        xr4.x += bl4.x + br4.x; xr4.y += bl4.y + br4.y;
        xr4.z += bl4.z + br4.z; xr4.w += bl4.w + br4.w;
    }
    float4 at4 = *(const float4*)(att + lane * 4);
    int beg = g_off[w], end = g_off[w + 1];

    float m = -INFINITY, d = 0.f;
    float4 acc = make_float4(0.f, 0.f, 0.f, 0.f);

    float4 aCur = *(const float4*)(ul + (size_t)g_csr[beg] * D + lane * 4);
    int sNext = (beg + 1 < end) ? g_csr[beg + 1] : 0;

    for (int e = beg; e < end; e++) {
        float4 a = aCur;
        if (e + 1 < end) {
            aCur = *(const float4*)(ul + (size_t)sNext * D + lane * 4);
            if (e + 2 < end) sNext = g_csr[e + 2];
        }
        float t0 = a.x + xr4.x; t0 = (t0 > 0.f) ? t0 : 0.2f * t0;
        float t1 = a.y + xr4.y; t1 = (t1 > 0.f) ? t1 : 0.2f * t1;
        float t2 = a.z + xr4.z; t2 = (t2 > 0.f) ? t2 : 0.2f * t2;
        float t3 = a.w + xr4.w; t3 = (t3 > 0.f) ? t3 : 0.2f * t3;
        float p = t0 * at4.x + t1 * at4.y + t2 * at4.z + t3 * at4.w;
        #pragma unroll
        for (int o = 16; o; o >>= 1) p += __shfl_xor_sync(0xffffffffu, p, o);

        if (p <= m) {
            float wgt = __expf(p - m);
            d += wgt;
            acc.x += wgt * a.x; acc.y += wgt * a.y;
            acc.z += wgt * a.z; acc.w += wgt * a.w;
        } else {
            float c1 = __expf(m - p);
            d = d * c1 + 1.f;
            acc.x = acc.x * c1 + a.x; acc.y = acc.y * c1 + a.y;
            acc.z = acc.z * c1 + a.z; acc.w = acc.w * c1 + a.w;
            m = p;
        }
    }

    float inv = 1.f / (d + 1e-16f);
    float4 bo4 = *(const float4*)(bo + lane * 4);
    float4 fw = *(const float4*)(fcW + lane * 4);
    float v = (acc.x * inv + bl4.x + bo4.x) * fw.x
            + (acc.y * inv + bl4.y + bo4.y) * fw.y
            + (acc.z * inv + bl4.z + bo4.z) * fw.z
            + (acc.w * inv + bl4.w + bo4.w) * fw.w;
    #pragma unroll
    for (int o = 16; o; o >>= 1) v += __shfl_xor_sync(0xffffffffu, v, o);
    if (lane == 0) value[w] = v + fcb[0];
}

// ---------------- fused actor head: a2 projections + gat7 on 32 targets ------
__global__ void k_actorhead(const float* __restrict__ h,
                            const float* __restrict__ W1, const float* __restrict__ b1,
                            const float* __restrict__ W2, const float* __restrict__ b2,
                            const float* __restrict__ att, const float* __restrict__ bias,
                            float* __restrict__ lg, int B, int N) {
    __shared__ float W1s[D * CH], W2s[D * CH];
    int t = blockIdx.x;          // 0..B*NC-1
    int lane = threadIdx.x;      // 32 threads
    for (int i = lane; i < D * CH; i += 32) { W1s[i] = W1[i]; W2s[i] = W2[i]; }
    __syncwarp();

    int row = (t >> 3) * N + (t & 7);
    int k0 = lane * 4;

    float4 hr = *(const float4*)(h + (size_t)row * D + k0);
    float s2v[CH], attv[CH], b1v[CH];
    #pragma unroll
    for (int c = 0; c < CH; c++) {
        float p = hr.x * W2s[(k0 + 0) * CH + c] + hr.y * W2s[(k0 + 1) * CH + c]
                + hr.z * W2s[(k0 + 2) * CH + c] + hr.w * W2s[(k0 + 3) * CH + c];
        #pragma unroll
        for (int o = 16; o; o >>= 1) p += __shfl_xor_sync(0xffffffffu, p, o);
        s2v[c] = p + b2[c];
        attv[c] = att[c];
        b1v[c] = b1[c];
    }

    int beg = g_off[row], end = g_off[row + 1];
    float m = -INFINITY, d = 0.f;
    float acc[CH];
    #pragma unroll
    for (int c = 0; c < CH; c++) acc[c] = 0.f;

    for (int e = beg; e < end; e++) {
        int s = g_csr[e];
        float4 hs = *(const float4*)(h + (size_t)s * D + k0);
        float s1v[CH];
        #pragma unroll
        for (int c = 0; c < CH; c++) {
            float p = hs.x * W1s[(k0 + 0) * CH + c] + hs.y * W1s[(k0 + 1) * CH + c]
                    + hs.z * W1s[(k0 + 2) * CH + c] + hs.w * W1s[(k0 + 3) * CH + c];
            #pragma unroll
            for (int o = 16; o; o >>= 1) p += __shfl_xor_sync(0xffffffffu, p, o);
            s1v[c] = p + b1v[c];
        }
        float sc = 0.f;
        #pragma unroll
        for (int c = 0; c < CH; c++) {
            float tt = s1v[c] + s2v[c];
            tt = (tt > 0.f) ? tt : 0.2f * tt;
            sc = fmaf(tt, attv[c], sc);
        }
        if (sc <= m) {
            float wgt = __expf(sc - m);
            d += wgt;
            #pragma unroll
            for (int c = 0; c < CH; c++) acc[c] = fmaf(wgt, s1v[c], acc[c]);
        } else {
            float c1 = __expf(m - sc);
            d = d * c1 + 1.f;
            #pragma unroll
            for (int c = 0; c < CH; c++) acc[c] = acc[c] * c1 + s1v[c];
            m = sc;
        }
    }
    if (lane == 0) {
        float inv = 1.f / (d + 1e-16f);
        for (int c = 0; c < CH; c++)
            lg[t * CH + c] = acc[c] * inv + bias[c];
    }
}

// ---------------- actor head: softmax + gumbel + top-4 + sel -----------------
__global__ void k_actor(const float* __restrict__ logits, const float* __restrict__ gu,
                        float* __restrict__ out, int B, int N) {
    __shared__ float shp[4][NC][CH];
    int tid = threadIdx.x;            // 32 threads
    int b = tid >> 3, i = tid & 7;
    bool active = tid < B * NC;
    if (active) {
        float l[CH], mx = -INFINITY;
        for (int c = 0; c < CH; c++) { l[c] = logits[tid * CH + c]; mx = fmaxf(mx, l[c]); }
        float s = 0.f;
        for (int c = 0; c < CH; c++) { l[c] = expf(l[c] - mx); s += l[c]; }
        for (int c = 0; c < CH; c++) shp[b][i][c] = l[c] / s;
    }
    __syncthreads();
    if (active) {
        float sc[CH];
        for (int c = 0; c < CH; c++) {
            float u = gu[(b * NC + i) * CH + c];
            float g = -logf(-logf(u));
            sc[c] = logf(shp[b][i][c]) + g;
        }
        int base = (b * NC + i) * NS;
        int seloff = B * NC * NS;
        for (int j = 0; j < NS; j++) {
            int best = 0; float bv = -INFINITY;
            for (int c = 0; c < CH; c++)
                if (sc[c] > bv) { bv = sc[c]; best = c; }
            out[base + j] = (float)best;
            out[seloff + base + j] = shp[b][best][j];
            sc[best] = -INFINITY;
        }
    }
}

// ---------------- launch -----------------------------------------------------
extern "C" void kernel_launch(void* const* d_in, const int* in_sizes, int n_in,
                              void* d_out, int out_size) {
    const float* x  = (const float*)d_in[0];
    const int*   ei = (const int*)d_in[1];
    const float* gu = (const float*)d_in[2];
    const float* Wp[4][6];
    for (int l = 0; l < 4; l++)
        for (int j = 0; j < 6; j++)
            Wp[l][j] = (const float*)d_in[3 + l * 6 + j];
    const float* fcW = (const float*)d_in[27];
    const float* fcb = (const float*)d_in[28];

    int M = in_sizes[0] / D;
    int E = in_sizes[1] / 2;
    int B = in_sizes[2] / (NC * CH);
    int N = M / B;
    int ET = E + M;
    float* out = (float*)d_out;

    // one-time (first/correctness call, before graph capture) stream+event setup
    static cudaStream_t s1 = nullptr, s2 = nullptr, s3 = nullptr;
    static cudaEvent_t evA = nullptr, evB0 = nullptr, evB = nullptr,
                       evC0 = nullptr, evE0 = nullptr, evD = nullptr;
    if (!s1) {
        cudaStreamCreateWithFlags(&s1, cudaStreamNonBlocking);
        cudaStreamCreateWithFlags(&s2, cudaStreamNonBlocking);
        cudaStreamCreateWithFlags(&s3, cudaStreamNonBlocking);
        cudaEventCreateWithFlags(&evA, cudaEventDisableTiming);
        cudaEventCreateWithFlags(&evB0, cudaEventDisableTiming);
        cudaEventCreateWithFlags(&evB, cudaEventDisableTiming);
        cudaEventCreateWithFlags(&evC0, cudaEventDisableTiming);
        cudaEventCreateWithFlags(&evE0, cudaEventDisableTiming);
        cudaEventCreateWithFlags(&evD, cudaEventDisableTiming);
    }

    void *pc, *pwlc, *pwl2c, *pxlA, *pxrA, *pxlC, *pxrC, *pyl, *pyr, *phA, *phC, *plg;
    cudaGetSymbolAddress(&pc,    g_count);
    cudaGetSymbolAddress(&pwlc,  g_wlcount);
    cudaGetSymbolAddress(&pwl2c, g_wl2count);
    cudaGetSymbolAddress(&pxlA,  g_xlA);
    cudaGetSymbolAddress(&pxrA,  g_xrA);
    cudaGetSymbolAddress(&pxlC,  g_xlC);
    cudaGetSymbolAddress(&pxrC,  g_xrC);
    cudaGetSymbolAddress(&pyl,   g_yl);
    cudaGetSymbolAddress(&pyr,   g_yr);
    cudaGetSymbolAddress(&phA,   g_hA);
    cudaGetSymbolAddress(&phC,   g_hC);
    cudaGetSymbolAddress(&plg,   g_lg);
    float* xlA = (float*)pxlA; float* xrA = (float*)pxrA;
    float* xlC = (float*)pxlC; float* xrC = (float*)pxrC;
    float* yl  = (float*)pyl;  float* yr  = (float*)pyr;
    float* hA  = (float*)phA;  float* hC  = (float*)phC;
    float* lg  = (float*)plg;

    const int tb = 256;
    size_t smemN = (size_t)4 * 128 * LDB * sizeof(__nv_bfloat16);  // 139264
    cudaFuncSetAttribute(k_gemmN, cudaFuncAttributeMaxDynamicSharedMemorySize, (int)smemN);
    int gg  = (M + 127) / 128;
    int gE  = (ET + tb - 1) / tb; if (gE > 4096) gE = 4096;

    int Mh = (((M + 1) / 2 + 127) / 128) * 128;   // chunk split, 128-aligned
    if (Mh > M) Mh = M;
    int ggh0 = (Mh + 127) / 128;
    int ggh1 = (M - Mh + 127) / 128;
    int gw0  = (Mh * 32 + tb - 1) / tb;
    int gw1  = ((M - Mh) * 32 + tb - 1) / tb;
    int gwB  = (M * 32 + tb - 1) / tb;
    int gwl  = (WLMAX * 32 + tb - 1) / tb;

    // ---- fork: CSR build (s1) || dense critic layer-1 GEMM (main) ----
    cudaEventRecord(evA, 0);
    cudaStreamWaitEvent(s1, evA, 0);

    cudaMemsetAsync(pc, 0, (size_t)(M + 1) * sizeof(int), s1);
    k_hist<<<gE, tb, 0, s1>>>(ei + E, E, M);
    k_scan<<<1, 1024, 0, s1>>>(M);
    k_scatter<<<gE, tb, 0, s1>>>(ei, ei + E, E, M);
    k_sortwarp<<<gw0, tb, 0, s1>>>(0, Mh);       // sort rows [0, Mh) first
    cudaEventRecord(evB0, s1);
    if (M > Mh)
        k_sortwarp<<<gw1, tb, 0, s1>>>(Mh, M);
    cudaEventRecord(evB, s1);

    k_gemmN<<<gg, tb, smemN>>>(x, Wp[2][0], xlC, Wp[2][2], xrC, M);

    // ---- actor branch (s3): wl -> wl2 -> fp32 proj(2-hop) -> gat(wl) -> head
    cudaStreamWaitEvent(s3, evB, 0);
    cudaMemsetAsync(pwlc, 0, sizeof(int), s3);
    cudaMemsetAsync(pwl2c, 0, sizeof(int), s3);
    k_mkwl<<<1, 1024, 0, s3>>>(B, N);
    k_mkwl2<<<gwl, tb, 0, s3>>>();
    k_projwl<<<256, 256, 0, s3>>>(x, Wp[0][0], Wp[0][2], xlA, xrA);
    k_gat1wl<<<gwl, tb, 0, s3>>>(xlA, xrA, Wp[0][4], Wp[0][1], Wp[0][3], Wp[0][5],
                                 hA, 0.01f);
    k_actorhead<<<B * NC, 32, 0, s3>>>(hA, Wp[1][0], Wp[1][1], Wp[1][2], Wp[1][3],
                                       Wp[1][4], Wp[1][5], lg, B, N);
    k_actor<<<1, 32, 0, s3>>>(lg, gu, out, B, N);
    cudaEventRecord(evD, s3);

    // ---- critic: chunked gatC (main), gemm2 chunk0 (s2) overlaps chunk1 ----
    cudaStreamWaitEvent(0, evB0, 0);
    k_gat1<<<gw0, tb>>>(xlC, xrC, Wp[2][4], Wp[2][1], Wp[2][3], Wp[2][5],
                        hC, 0, Mh, 0.01f);
    cudaEventRecord(evC0, 0);
    cudaStreamWaitEvent(0, evB, 0);
    if (M > Mh)
        k_gat1<<<gw1, tb>>>(xlC, xrC, Wp[2][4], Wp[2][1], Wp[2][3], Wp[2][5],
                            hC, Mh, M, 0.01f);

    cudaStreamWaitEvent(s2, evC0, 0);
    k_gemmN<<<ggh0, tb, smemN, s2>>>(hC, Wp[3][0], yl, Wp[3][2], yr, Mh);
    cudaEventRecord(evE0, s2);

    // gemm2 chunk1 on main (after gatC chunk1; reads hC[Mh,M) only)
    if (M > Mh)
        k_gemmN<<<ggh1, tb, smemN>>>(hC + (size_t)Mh * D,
                                     Wp[3][0], yl + (size_t)Mh * D,
                                     Wp[3][2], yr + (size_t)Mh * D,
                                     M - Mh);

    // ---- gatV after both gemm2 chunks ----
    cudaStreamWaitEvent(0, evE0, 0);
    k_gatV<<<gwB, tb>>>(yl, yr, Wp[3][4], Wp[3][1], Wp[3][3], Wp[3][5],
                        fcW, fcb, out + 2 * B * NC * NS, M);

    // ---- final join ----
    cudaStreamWaitEvent(0, evD, 0);
}

// round 15
// speedup vs baseline: 1.0622x; 1.0622x over previous
#include <cuda_runtime.h>
#include <cuda_bf16.h>
#include <math.h>
#include <mma.h>

using namespace nvcuda;

#define D   128
#define CH  7
#define NC  8
#define NS  4
#define MAXM  40000
#define MP    (MAXM + 128)
#define MAXET 680000
#define WLMAX 8192

// ---------------- scratch (static device globals; no allocation) -------------
__device__ int   g_count[MAXM + 1];
__device__ int   g_off[MAXM + 1];
__device__ int   g_cursor[MAXM];
__device__ int   g_csr[MAXET];
__device__ int   g_wl[WLMAX];
__device__ int   g_wlcount;
__device__ float g_xlA[(size_t)MP * D];
__device__ float g_xrA[(size_t)MP * D];
__device__ float g_xlC[(size_t)MP * D];
__device__ float g_xrC[(size_t)MP * D];
__device__ float g_yl [(size_t)MP * D];   // critic layer-2 projections (race-safe)
__device__ float g_yr [(size_t)MP * D];
__device__ float g_hA [(size_t)MP * D];
__device__ float g_hC [(size_t)MP * D];
__device__ float g_lg[64 * CH];

// ---------------- CSR build --------------------------------------------------
__global__ void k_hist(const int* __restrict__ tgt, int E, int M) {
    int stride = gridDim.x * blockDim.x;
    int ET = E + M;
    for (int i = blockIdx.x * blockDim.x + threadIdx.x; i < ET; i += stride) {
        int t = (i < E) ? tgt[i] : (i - E);
        atomicAdd(&g_count[t], 1);
    }
}

__global__ void k_scan(int M) {  // single block, 1024 threads
    __shared__ int sh[1024];
    int tid = threadIdx.x;
    int chunk = (M + 1023) >> 10;
    int beg = tid * chunk;
    int end = min(beg + chunk, M);
    int s = 0;
    for (int i = beg; i < end; i++) s += g_count[i];
    sh[tid] = s;
    __syncthreads();
    for (int o = 1; o < 1024; o <<= 1) {
        int v = (tid >= o) ? sh[tid - o] : 0;
        __syncthreads();
        sh[tid] += v;
        __syncthreads();
    }
    int run = sh[tid] - s;
    for (int i = beg; i < end; i++) {
        g_off[i] = run;
        g_cursor[i] = run;
        run += g_count[i];
    }
    if (tid == 1023) g_off[M] = sh[1023];
}

__global__ void k_scatter(const int* __restrict__ src, const int* __restrict__ tgt,
                          int E, int M) {
    int stride = gridDim.x * blockDim.x;
    int ET = E + M;
    for (int i = blockIdx.x * blockDim.x + threadIdx.x; i < ET; i += stride) {
        int t, s;
        if (i < E) { t = tgt[i]; s = src[i]; }
        else       { t = i - E;  s = i - E; }
        int pos = atomicAdd(&g_cursor[t], 1);
        g_csr[pos] = s;
    }
}

// warp-per-node segment sort (bitonic shfl for deg<=32; insertion fallback).
// Deterministic CSR order -> bitwise-stable downstream accumulation.
__global__ void k_sortwarp(int M) {
    int w = (blockIdx.x * blockDim.x + threadIdx.x) >> 5;
    if (w >= M) return;
    int lane = threadIdx.x & 31;
    int beg = g_off[w], end = g_off[w + 1];
    int deg = end - beg;
    if (deg <= 1) return;
    if (deg <= 32) {
        int v = (lane < deg) ? g_csr[beg + lane] : 0x7fffffff;
        #pragma unroll
        for (int k = 2; k <= 32; k <<= 1) {
            #pragma unroll
            for (int j = k >> 1; j > 0; j >>= 1) {
                int partner = __shfl_xor_sync(0xffffffffu, v, j);
                bool dir   = ((lane & k) == 0);
                bool lower = ((lane & j) == 0);
                v = (lower == dir) ? min(v, partner) : max(v, partner);
            }
        }
        if (lane < deg) g_csr[beg + lane] = v;
    } else if (lane == 0) {
        for (int i = beg + 1; i < end; i++) {
            int v = g_csr[i]; int j = i - 1;
            while (j >= beg && g_csr[j] > v) { g_csr[j + 1] = g_csr[j]; j--; }
            g_csr[j + 1] = v;
        }
    }
}

// ---------------- actor worklist: 32 targets + their sources -----------------
__global__ void k_mkwl(int B, int N) {
    int t = threadIdx.x >> 5;     // one block, 1024 threads
    int lane = threadIdx.x & 31;
    if (t >= B * NC) return;
    int row = (t >> 3) * N + (t & 7);
    int beg = g_off[row], end = g_off[row + 1];
    int deg = end - beg;
    int pos = 0;
    if (lane == 0) pos = atomicAdd(&g_wlcount, deg + 1);
    pos = __shfl_sync(0xffffffffu, pos, 0);
    for (int i = lane; i < deg + 1; i += 32) {
        int idx = pos + i;
        if (idx < WLMAX)
            g_wl[idx] = (i == 0) ? row : g_csr[beg + i - 1];
    }
}

// ---------------- bf16x3 tensor-core multi-GEMM (no bias, direct store) ------
#define LDB 136

__device__ __forceinline__ void split_store4(float4 v, __nv_bfloat16* hi,
                                             __nv_bfloat16* lo, int idx) {
    __nv_bfloat16 h0 = __float2bfloat16(v.x), h1 = __float2bfloat16(v.y),
                  h2 = __float2bfloat16(v.z), h3 = __float2bfloat16(v.w);
    float l0 = v.x - __bfloat162float(h0), l1 = v.y - __bfloat162float(h1),
          l2 = v.z - __bfloat162float(h2), l3 = v.w - __bfloat162float(h3);
    __nv_bfloat162 hp0 = __halves2bfloat162(h0, h1), hp1 = __halves2bfloat162(h2, h3);
    uint2 hv; hv.x = *(unsigned*)&hp0; hv.y = *(unsigned*)&hp1;
    *(uint2*)&hi[idx] = hv;
    __nv_bfloat162 lp0 = __floats2bfloat162_rn(l0, l1), lp1 = __floats2bfloat162_rn(l2, l3);
    uint2 lv; lv.x = *(unsigned*)&lp0; lv.y = *(unsigned*)&lp1;
    *(uint2*)&lo[idx] = lv;
}

__global__ void k_gemmN(const float* __restrict__ A,
                        const float* __restrict__ W0, float* __restrict__ C0,
                        const float* __restrict__ W1, float* __restrict__ C1,
                        const float* __restrict__ W2, float* __restrict__ C2,
                        const float* __restrict__ W3, float* __restrict__ C3,
                        int M, int npass) {
    extern __shared__ char smraw[];
    __nv_bfloat16* Ahi = (__nv_bfloat16*)smraw;
    __nv_bfloat16* Alo = Ahi + 128 * LDB;
    __nv_bfloat16* Whi = Alo + 128 * LDB;
    __nv_bfloat16* Wlo = Whi + 128 * LDB;

    int tid = threadIdx.x;       // 256
    int row0 = blockIdx.x * 128;
    int r = tid >> 1, half = tid & 1;
    int cbase = half * 64;

    const float* Wt[4] = {W0, W1, W2, W3};
    float*       Ct[4] = {C0, C1, C2, C3};

    {
        int row = row0 + r;
        const float* ap = A + (size_t)row * D + cbase;
        #pragma unroll
        for (int q = 0; q < 16; q++) {
            float4 v = (row < M) ? *(const float4*)(ap + q * 4)
                                 : make_float4(0.f, 0.f, 0.f, 0.f);
            split_store4(v, Ahi, Alo, r * LDB + cbase + q * 4);
        }
    }

    int w  = tid >> 5;
    int wr = w >> 2, wc = w & 3;   // warp tile: 64 rows x 32 cols

    for (int pass = 0; pass < npass; pass++) {
        const float* W = Wt[pass];
        float* C       = Ct[pass];

        if (pass > 0) __syncthreads();
        {
            const float* wp = W + r * D + cbase;
            #pragma unroll
            for (int q = 0; q < 16; q++)
                split_store4(*(const float4*)(wp + q * 4), Whi, Wlo,
                             r * LDB + cbase + q * 4);
        }
        __syncthreads();

        wmma::fragment<wmma::accumulator, 16, 16, 16, float> acc[4][2];
        #pragma unroll
        for (int m = 0; m < 4; m++)
            #pragma unroll
            for (int n = 0; n < 2; n++) wmma::fill_fragment(acc[m][n], 0.f);

        wmma::fragment<wmma::matrix_a, 16, 16, 16, __nv_bfloat16, wmma::row_major> ah[4], al[4];
        wmma::fragment<wmma::matrix_b, 16, 16, 16, __nv_bfloat16, wmma::row_major> bh[2], bl[2];

        #pragma unroll
        for (int kk = 0; kk < 8; kk++) {
            int k0 = kk * 16;
            #pragma unroll
            for (int n = 0; n < 2; n++) {
                wmma::load_matrix_sync(bh[n], &Whi[k0 * LDB + wc * 32 + n * 16], LDB);
                wmma::load_matrix_sync(bl[n], &Wlo[k0 * LDB + wc * 32 + n * 16], LDB);
            }
            #pragma unroll
            for (int m = 0; m < 4; m++) {
                wmma::load_matrix_sync(ah[m], &Ahi[(wr * 64 + m * 16) * LDB + k0], LDB);
                wmma::load_matrix_sync(al[m], &Alo[(wr * 64 + m * 16) * LDB + k0], LDB);
            }
            #pragma unroll
            for (int m = 0; m < 4; m++)
                #pragma unroll
                for (int n = 0; n < 2; n++) {
                    wmma::mma_sync(acc[m][n], ah[m], bl[n], acc[m][n]);
                    wmma::mma_sync(acc[m][n], al[m], bh[n], acc[m][n]);
                    wmma::mma_sync(acc[m][n], ah[m], bh[n], acc[m][n]);
                }
        }

        #pragma unroll
        for (int m = 0; m < 4; m++)
            #pragma unroll
            for (int n = 0; n < 2; n++)
                wmma::store_matrix_sync(
                    C + (size_t)(row0 + wr * 64 + m * 16) * D + wc * 32 + n * 16,
                    acc[m][n], D, wmma::mem_row_major);
    }
}

// ---------------- GATv2 node body (bias-folded, prefetch) --------------------
__device__ __forceinline__ void gat_node(
    int w, int lane,
    const float* __restrict__ ul, const float* __restrict__ ur,
    const float* __restrict__ att, const float* __restrict__ bl,
    const float* __restrict__ br, const float* __restrict__ bo,
    float* __restrict__ out, float slope) {
    float4 bl4 = *(const float4*)(bl + lane * 4);
    float4 xr4 = *(const float4*)(ur + (size_t)w * D + lane * 4);
    {
        float4 br4 = *(const float4*)(br + lane * 4);
        xr4.x += bl4.x + br4.x; xr4.y += bl4.y + br4.y;
        xr4.z += bl4.z + br4.z; xr4.w += bl4.w + br4.w;
    }
    float4 at4 = *(const float4*)(att + lane * 4);
    int beg = g_off[w], end = g_off[w + 1];

    float m = -INFINITY, d = 0.f;
    float4 acc = make_float4(0.f, 0.f, 0.f, 0.f);

    float4 aCur = *(const float4*)(ul + (size_t)g_csr[beg] * D + lane * 4);
    int sNext = (beg + 1 < end) ? g_csr[beg + 1] : 0;

    for (int e = beg; e < end; e++) {
        float4 a = aCur;
        if (e + 1 < end) {
            aCur = *(const float4*)(ul + (size_t)sNext * D + lane * 4);
            if (e + 2 < end) sNext = g_csr[e + 2];
        }
        float t0 = a.x + xr4.x; t0 = (t0 > 0.f) ? t0 : 0.2f * t0;
        float t1 = a.y + xr4.y; t1 = (t1 > 0.f) ? t1 : 0.2f * t1;
        float t2 = a.z + xr4.z; t2 = (t2 > 0.f) ? t2 : 0.2f * t2;
        float t3 = a.w + xr4.w; t3 = (t3 > 0.f) ? t3 : 0.2f * t3;
        float p = t0 * at4.x + t1 * at4.y + t2 * at4.z + t3 * at4.w;
        #pragma unroll
        for (int o = 16; o; o >>= 1) p += __shfl_xor_sync(0xffffffffu, p, o);

        if (p <= m) {
            float wgt = __expf(p - m);
            d += wgt;
            acc.x += wgt * a.x; acc.y += wgt * a.y;
            acc.z += wgt * a.z; acc.w += wgt * a.w;
        } else {
            float c1 = __expf(m - p);
            d = d * c1 + 1.f;
            acc.x = acc.x * c1 + a.x; acc.y = acc.y * c1 + a.y;
            acc.z = acc.z * c1 + a.z; acc.w = acc.w * c1 + a.w;
            m = p;
        }
    }

    float inv = 1.f / (d + 1e-16f);
    float4 bo4 = *(const float4*)(bo + lane * 4);
    float o0 = acc.x * inv + bl4.x + bo4.x;
    float o1 = acc.y * inv + bl4.y + bo4.y;
    float o2 = acc.z * inv + bl4.z + bo4.z;
    float o3 = acc.w * inv + bl4.w + bo4.w;
    o0 = (o0 > 0.f) ? o0 : slope * o0;
    o1 = (o1 > 0.f) ? o1 : slope * o1;
    o2 = (o2 > 0.f) ? o2 : slope * o2;
    o3 = (o3 > 0.f) ? o3 : slope * o3;
    *(float4*)(out + (size_t)w * D + lane * 4) = make_float4(o0, o1, o2, o3);
}

__global__ void k_gat1(
    const float* __restrict__ ul, const float* __restrict__ ur,
    const float* __restrict__ att, const float* __restrict__ bl,
    const float* __restrict__ br, const float* __restrict__ bo,
    float* __restrict__ out, int w0, int wEnd, float slope) {
    int w = w0 + ((blockIdx.x * blockDim.x + threadIdx.x) >> 5);
    if (w >= wEnd) return;
    gat_node(w, threadIdx.x & 31, ul, ur, att, bl, br, bo, out, slope);
}

__global__ void k_gat1wl(
    const float* __restrict__ ul, const float* __restrict__ ur,
    const float* __restrict__ att, const float* __restrict__ bl,
    const float* __restrict__ br, const float* __restrict__ bo,
    float* __restrict__ out, float slope) {
    int idx = (blockIdx.x * blockDim.x + threadIdx.x) >> 5;
    int n = g_wlcount; if (n > WLMAX) n = WLMAX;
    if (idx >= n) return;
    gat_node(g_wl[idx], threadIdx.x & 31, ul, ur, att, bl, br, bo, out, slope);
}

// ---------------- c2 GATv2 + fused value head --------------------------------
__global__ void k_gatV(
    const float* __restrict__ ul, const float* __restrict__ ur,
    const float* __restrict__ att, const float* __restrict__ bl,
    const float* __restrict__ br, const float* __restrict__ bo,
    const float* __restrict__ fcW, const float* __restrict__ fcb,
    float* __restrict__ value, int M) {
    int w = (blockIdx.x * blockDim.x + threadIdx.x) >> 5;
    if (w >= M) return;
    int lane = threadIdx.x & 31;

    float4 bl4 = *(const float4*)(bl + lane * 4);
    float4 xr4 = *(const float4*)(ur + (size_t)w * D + lane * 4);
    {
        float4 br4 = *(const float4*)(br + lane * 4);
        xr4.x += bl4.x + br4.x; xr4.y += bl4.y + br4.y;
        xr4.z += bl4.z + br4.z; xr4.w += bl4.w + br4.w;
    }
    float4 at4 = *(const float4*)(att + lane * 4);
    int beg = g_off[w], end = g_off[w + 1];

    float m = -INFINITY, d = 0.f;
    float4 acc = make_float4(0.f, 0.f, 0.f, 0.f);

    float4 aCur = *(const float4*)(ul + (size_t)g_csr[beg] * D + lane * 4);
    int sNext = (beg + 1 < end) ? g_csr[beg + 1] : 0;

    for (int e = beg; e < end; e++) {
        float4 a = aCur;
        if (e + 1 < end) {
            aCur = *(const float4*)(ul + (size_t)sNext * D + lane * 4);
            if (e + 2 < end) sNext = g_csr[e + 2];
        }
        float t0 = a.x + xr4.x; t0 = (t0 > 0.f) ? t0 : 0.2f * t0;
        float t1 = a.y + xr4.y; t1 = (t1 > 0.f) ? t1 : 0.2f * t1;
        float t2 = a.z + xr4.z; t2 = (t2 > 0.f) ? t2 : 0.2f * t2;
        float t3 = a.w + xr4.w; t3 = (t3 > 0.f) ? t3 : 0.2f * t3;
        float p = t0 * at4.x + t1 * at4.y + t2 * at4.z + t3 * at4.w;
        #pragma unroll
        for (int o = 16; o; o >>= 1) p += __shfl_xor_sync(0xffffffffu, p, o);

        if (p <= m) {
            float wgt = __expf(p - m);
            d += wgt;
            acc.x += wgt * a.x; acc.y += wgt * a.y;
            acc.z += wgt * a.z; acc.w += wgt * a.w;
        } else {
            float c1 = __expf(m - p);
            d = d * c1 + 1.f;
            acc.x = acc.x * c1 + a.x; acc.y = acc.y * c1 + a.y;
            acc.z = acc.z * c1 + a.z; acc.w = acc.w * c1 + a.w;
            m = p;
        }
    }

    float inv = 1.f / (d + 1e-16f);
    float4 bo4 = *(const float4*)(bo + lane * 4);
    float4 fw = *(const float4*)(fcW + lane * 4);
    float v = (acc.x * inv + bl4.x + bo4.x) * fw.x
            + (acc.y * inv + bl4.y + bo4.y) * fw.y
            + (acc.z * inv + bl4.z + bo4.z) * fw.z
            + (acc.w * inv + bl4.w + bo4.w) * fw.w;
    #pragma unroll
    for (int o = 16; o; o >>= 1) v += __shfl_xor_sync(0xffffffffu, v, o);
    if (lane == 0) value[w] = v + fcb[0];
}

// ---------------- fused actor head: a2 projections + gat7 on 32 targets ------
__global__ void k_actorhead(const float* __restrict__ h,
                            const float* __restrict__ W1, const float* __restrict__ b1,
                            const float* __restrict__ W2, const float* __restrict__ b2,
                            const float* __restrict__ att, const float* __restrict__ bias,
                            float* __restrict__ lg, int B, int N) {
    __shared__ float W1s[D * CH], W2s[D * CH];
    int t = blockIdx.x;          // 0..B*NC-1
    int lane = threadIdx.x;      // 32 threads
    for (int i = lane; i < D * CH; i += 32) { W1s[i] = W1[i]; W2s[i] = W2[i]; }
    __syncwarp();

    int row = (t >> 3) * N + (t & 7);
    int k0 = lane * 4;

    float4 hr = *(const float4*)(h + (size_t)row * D + k0);
    float s2v[CH], attv[CH], b1v[CH];
    #pragma unroll
    for (int c = 0; c < CH; c++) {
        float p = hr.x * W2s[(k0 + 0) * CH + c] + hr.y * W2s[(k0 + 1) * CH + c]
                + hr.z * W2s[(k0 + 2) * CH + c] + hr.w * W2s[(k0 + 3) * CH + c];
        #pragma unroll
        for (int o = 16; o; o >>= 1) p += __shfl_xor_sync(0xffffffffu, p, o);
        s2v[c] = p + b2[c];
        attv[c] = att[c];
        b1v[c] = b1[c];
    }

    int beg = g_off[row], end = g_off[row + 1];
    float m = -INFINITY, d = 0.f;
    float acc[CH];
    #pragma unroll
    for (int c = 0; c < CH; c++) acc[c] = 0.f;

    for (int e = beg; e < end; e++) {
        int s = g_csr[e];
        float4 hs = *(const float4*)(h + (size_t)s * D + k0);
        float s1v[CH];
        #pragma unroll
        for (int c = 0; c < CH; c++) {
            float p = hs.x * W1s[(k0 + 0) * CH + c] + hs.y * W1s[(k0 + 1) * CH + c]
                    + hs.z * W1s[(k0 + 2) * CH + c] + hs.w * W1s[(k0 + 3) * CH + c];
            #pragma unroll
            for (int o = 16; o; o >>= 1) p += __shfl_xor_sync(0xffffffffu, p, o);
            s1v[c] = p + b1v[c];
        }
        float sc = 0.f;
        #pragma unroll
        for (int c = 0; c < CH; c++) {
            float tt = s1v[c] + s2v[c];
            tt = (tt > 0.f) ? tt : 0.2f * tt;
            sc = fmaf(tt, attv[c], sc);
        }
        if (sc <= m) {
            float wgt = __expf(sc - m);
            d += wgt;
            #pragma unroll
            for (int c = 0; c < CH; c++) acc[c] = fmaf(wgt, s1v[c], acc[c]);
        } else {
            float c1 = __expf(m - sc);
            d = d * c1 + 1.f;
            #pragma unroll
            for (int c = 0; c < CH; c++) acc[c] = acc[c] * c1 + s1v[c];
            m = sc;
        }
    }
    if (lane == 0) {
        float inv = 1.f / (d + 1e-16f);
        for (int c = 0; c < CH; c++)
            lg[t * CH + c] = acc[c] * inv + bias[c];
    }
}

// ---------------- actor head: softmax + gumbel + top-4 + sel -----------------
__global__ void k_actor(const float* __restrict__ logits, const float* __restrict__ gu,
                        float* __restrict__ out, int B, int N) {
    __shared__ float shp[4][NC][CH];
    int tid = threadIdx.x;            // 32 threads
    int b = tid >> 3, i = tid & 7;
    bool active = tid < B * NC;
    if (active) {
        float l[CH], mx = -INFINITY;
        for (int c = 0; c < CH; c++) { l[c] = logits[tid * CH + c]; mx = fmaxf(mx, l[c]); }
        float s = 0.f;
        for (int c = 0; c < CH; c++) { l[c] = expf(l[c] - mx); s += l[c]; }
        for (int c = 0; c < CH; c++) shp[b][i][c] = l[c] / s;
    }
    __syncthreads();
    if (active) {
        float sc[CH];
        for (int c = 0; c < CH; c++) {
            float u = gu[(b * NC + i) * CH + c];
            float g = -logf(-logf(u));
            sc[c] = logf(shp[b][i][c]) + g;
        }
        int base = (b * NC + i) * NS;
        int seloff = B * NC * NS;
        for (int j = 0; j < NS; j++) {
            int best = 0; float bv = -INFINITY;
            for (int c = 0; c < CH; c++)
                if (sc[c] > bv) { bv = sc[c]; best = c; }
            out[base + j] = (float)best;
            out[seloff + base + j] = shp[b][best][j];
            sc[best] = -INFINITY;
        }
    }
}

// ---------------- launch -----------------------------------------------------
extern "C" void kernel_launch(void* const* d_in, const int* in_sizes, int n_in,
                              void* d_out, int out_size) {
    const float* x  = (const float*)d_in[0];
    const int*   ei = (const int*)d_in[1];
    const float* gu = (const float*)d_in[2];
    const float* Wp[4][6];
    for (int l = 0; l < 4; l++)
        for (int j = 0; j < 6; j++)
            Wp[l][j] = (const float*)d_in[3 + l * 6 + j];
    const float* fcW = (const float*)d_in[27];
    const float* fcb = (const float*)d_in[28];

    int M = in_sizes[0] / D;
    int E = in_sizes[1] / 2;
    int B = in_sizes[2] / (NC * CH);
    int N = M / B;
    int ET = E + M;
    float* out = (float*)d_out;

    // one-time (first/correctness call, before graph capture) stream+event setup
    static cudaStream_t s1 = nullptr, s2 = nullptr, s3 = nullptr;
    static cudaEvent_t evA = nullptr, evB = nullptr, evG4 = nullptr,
                       evC0 = nullptr, evC1 = nullptr, evE = nullptr, evD = nullptr;
    if (!s1) {
        cudaStreamCreateWithFlags(&s1, cudaStreamNonBlocking);
        cudaStreamCreateWithFlags(&s2, cudaStreamNonBlocking);
        cudaStreamCreateWithFlags(&s3, cudaStreamNonBlocking);
        cudaEventCreateWithFlags(&evA, cudaEventDisableTiming);
        cudaEventCreateWithFlags(&evB, cudaEventDisableTiming);
        cudaEventCreateWithFlags(&evG4, cudaEventDisableTiming);
        cudaEventCreateWithFlags(&evC0, cudaEventDisableTiming);
        cudaEventCreateWithFlags(&evC1, cudaEventDisableTiming);
        cudaEventCreateWithFlags(&evE, cudaEventDisableTiming);
        cudaEventCreateWithFlags(&evD, cudaEventDisableTiming);
    }

    void *pc, *pwlc, *pxlA, *pxrA, *pxlC, *pxrC, *pyl, *pyr, *phA, *phC, *plg;
    cudaGetSymbolAddress(&pc,   g_count);
    cudaGetSymbolAddress(&pwlc, g_wlcount);
    cudaGetSymbolAddress(&pxlA, g_xlA);
    cudaGetSymbolAddress(&pxrA, g_xrA);
    cudaGetSymbolAddress(&pxlC, g_xlC);
    cudaGetSymbolAddress(&pxrC, g_xrC);
    cudaGetSymbolAddress(&pyl,  g_yl);
    cudaGetSymbolAddress(&pyr,  g_yr);
    cudaGetSymbolAddress(&phA,  g_hA);
    cudaGetSymbolAddress(&phC,  g_hC);
    cudaGetSymbolAddress(&plg,  g_lg);
    float* xlA = (float*)pxlA; float* xrA = (float*)pxrA;
    float* xlC = (float*)pxlC; float* xrC = (float*)pxrC;
    float* yl  = (float*)pyl;  float* yr  = (float*)pyr;
    float* hA  = (float*)phA;  float* hC  = (float*)phC;
    float* lg  = (float*)plg;

    const int tb = 256;
    size_t smemN = (size_t)4 * 128 * LDB * sizeof(__nv_bfloat16);  // 139264
    cudaFuncSetAttribute(k_gemmN, cudaFuncAttributeMaxDynamicSharedMemorySize, (int)smemN);
    int gg  = (M + 127) / 128;
    int gE  = (ET + tb - 1) / tb; if (gE > 4096) gE = 4096;
    int gws = (M * 32 + tb - 1) / tb;

    int Mh = (((M + 1) / 2 + 127) / 128) * 128;   // chunk split, 128-aligned
    if (Mh > M) Mh = M;
    int ggh0 = (Mh + 127) / 128;
    int ggh1 = (M - Mh + 127) / 128;
    int gw0  = (Mh * 32 + tb - 1) / tb;
    int gw1  = ((M - Mh) * 32 + tb - 1) / tb;
    int gwB  = (M * 32 + tb - 1) / tb;
    int gwl  = (WLMAX * 32 + tb - 1) / tb;

    // ---- fork: CSR build (s1) || layer-1 GEMM (main) ----
    cudaEventRecord(evA, 0);
    cudaStreamWaitEvent(s1, evA, 0);

    cudaMemsetAsync(pc, 0, (size_t)(M + 1) * sizeof(int), s1);
    k_hist<<<gE, tb, 0, s1>>>(ei + E, E, M);
    k_scan<<<1, 1024, 0, s1>>>(M);
    k_scatter<<<gE, tb, 0, s1>>>(ei, ei + E, E, M);
    k_sortwarp<<<gws, tb, 0, s1>>>(M);
    cudaEventRecord(evB, s1);

    k_gemmN<<<gg, tb, smemN>>>(x, Wp[0][0], xlA, Wp[0][2], xrA,
                                  Wp[2][0], xlC, Wp[2][2], xrC, M, 4);
    cudaEventRecord(evG4, 0);

    // ---- actor branch (s3): worklist -> pruned gat -> head ----
    cudaStreamWaitEvent(s3, evB, 0);
    cudaStreamWaitEvent(s3, evG4, 0);
    cudaMemsetAsync(pwlc, 0, sizeof(int), s3);
    k_mkwl<<<1, 1024, 0, s3>>>(B, N);
    k_gat1wl<<<gwl, tb, 0, s3>>>(xlA, xrA, Wp[0][4], Wp[0][1], Wp[0][3], Wp[0][5],
                                 hA, 0.01f);
    k_actorhead<<<B * NC, 32, 0, s3>>>(hA, Wp[1][0], Wp[1][1], Wp[1][2], Wp[1][3],
                                       Wp[1][4], Wp[1][5], lg, B, N);
    k_actor<<<1, 32, 0, s3>>>(lg, gu, out, B, N);
    cudaEventRecord(evD, s3);

    // ---- critic: chunked gatC (main) pipelined with gemm2 (s2) ----
    cudaStreamWaitEvent(0, evB, 0);
    k_gat1<<<gw0, tb>>>(xlC, xrC, Wp[2][4], Wp[2][1], Wp[2][3], Wp[2][5],
                        hC, 0, Mh, 0.01f);
    cudaEventRecord(evC0, 0);
    if (M > Mh)
        k_gat1<<<gw1, tb>>>(xlC, xrC, Wp[2][4], Wp[2][1], Wp[2][3], Wp[2][5],
                            hC, Mh, M, 0.01f);
    cudaEventRecord(evC1, 0);

    cudaStreamWaitEvent(s2, evC0, 0);
    k_gemmN<<<ggh0, tb, smemN, s2>>>(hC, Wp[3][0], yl, Wp[3][2], yr,
                                         Wp[3][0], yl, Wp[3][2], yr, Mh, 2);
    cudaStreamWaitEvent(s2, evC1, 0);
    if (M > Mh)
        k_gemmN<<<ggh1, tb, smemN, s2>>>(hC + (size_t)Mh * D,
                                         Wp[3][0], yl + (size_t)Mh * D,
                                         Wp[3][2], yr + (size_t)Mh * D,
                                         Wp[3][0], yl + (size_t)Mh * D,
                                         Wp[3][2], yr + (size_t)Mh * D,
                                         M - Mh, 2);
    cudaEventRecord(evE, s2);

    // ---- gatV after full gemm2 ----
    cudaStreamWaitEvent(0, evE, 0);
    k_gatV<<<gwB, tb>>>(yl, yr, Wp[3][4], Wp[3][1], Wp[3][3], Wp[3][5],
                        fcW, fcb, out + 2 * B * NC * NS, M);

    // ---- final join ----
    cudaStreamWaitEvent(0, evD, 0);
}

// round 16
// speedup vs baseline: 1.1590x; 1.0912x over previous
#include <cuda_runtime.h>
#include <cuda_bf16.h>
#include <math.h>
#include <mma.h>

using namespace nvcuda;

#define D   128
#define CH  7
#define NC  8
#define NS  4
#define MAXM  40000
#define MP    (MAXM + 128)
#define MAXET 680000
#define WLMAX 8192

// ---------------- scratch (static device globals; no allocation) -------------
__device__ int   g_count[MAXM + 1];
__device__ int   g_off[MAXM + 1];
__device__ int   g_cursor[MAXM];
__device__ int   g_csr[MAXET];
__device__ int   g_wl[WLMAX];
__device__ int   g_wlcount;
__device__ float g_xlA[(size_t)MP * D];
__device__ float g_xrA[(size_t)MP * D];
__device__ float g_xlC[(size_t)MP * D];
__device__ float g_xrC[(size_t)MP * D];
__device__ float g_yl [(size_t)MP * D];   // critic layer-2 projections (race-safe)
__device__ float g_yr [(size_t)MP * D];
__device__ float g_hA [(size_t)MP * D];
__device__ float g_hC [(size_t)MP * D];
__device__ float g_lg[64 * CH];

// ---------------- CSR build --------------------------------------------------
__global__ void k_hist(const int* __restrict__ tgt, int E, int M) {
    int stride = gridDim.x * blockDim.x;
    int ET = E + M;
    for (int i = blockIdx.x * blockDim.x + threadIdx.x; i < ET; i += stride) {
        int t = (i < E) ? tgt[i] : (i - E);
        atomicAdd(&g_count[t], 1);
    }
}

__global__ void k_scan(int M) {  // single block, 1024 threads
    __shared__ int sh[1024];
    int tid = threadIdx.x;
    int chunk = (M + 1023) >> 10;
    int beg = tid * chunk;
    int end = min(beg + chunk, M);
    int s = 0;
    for (int i = beg; i < end; i++) s += g_count[i];
    sh[tid] = s;
    __syncthreads();
    for (int o = 1; o < 1024; o <<= 1) {
        int v = (tid >= o) ? sh[tid - o] : 0;
        __syncthreads();
        sh[tid] += v;
        __syncthreads();
    }
    int run = sh[tid] - s;
    for (int i = beg; i < end; i++) {
        g_off[i] = run;
        g_cursor[i] = run;
        run += g_count[i];
    }
    if (tid == 1023) g_off[M] = sh[1023];
}

__global__ void k_scatter(const int* __restrict__ src, const int* __restrict__ tgt,
                          int E, int M) {
    int stride = gridDim.x * blockDim.x;
    int ET = E + M;
    for (int i = blockIdx.x * blockDim.x + threadIdx.x; i < ET; i += stride) {
        int t, s;
        if (i < E) { t = tgt[i]; s = src[i]; }
        else       { t = i - E;  s = i - E; }
        int pos = atomicAdd(&g_cursor[t], 1);
        g_csr[pos] = s;
    }
}

// warp-per-node segment sort (bitonic shfl for deg<=32; insertion fallback).
// Deterministic CSR order -> bitwise-stable downstream accumulation.
__global__ void k_sortwarp(int M) {
    int w = (blockIdx.x * blockDim.x + threadIdx.x) >> 5;
    if (w >= M) return;
    int lane = threadIdx.x & 31;
    int beg = g_off[w], end = g_off[w + 1];
    int deg = end - beg;
    if (deg <= 1) return;
    if (deg <= 32) {
        int v = (lane < deg) ? g_csr[beg + lane] : 0x7fffffff;
        #pragma unroll
        for (int k = 2; k <= 32; k <<= 1) {
            #pragma unroll
            for (int j = k >> 1; j > 0; j >>= 1) {
                int partner = __shfl_xor_sync(0xffffffffu, v, j);
                bool dir   = ((lane & k) == 0);
                bool lower = ((lane & j) == 0);
                v = (lower == dir) ? min(v, partner) : max(v, partner);
            }
        }
        if (lane < deg) g_csr[beg + lane] = v;
    } else if (lane == 0) {
        for (int i = beg + 1; i < end; i++) {
            int v = g_csr[i]; int j = i - 1;
            while (j >= beg && g_csr[j] > v) { g_csr[j + 1] = g_csr[j]; j--; }
            g_csr[j + 1] = v;
        }
    }
}

// ---------------- actor worklist: 32 targets + their sources -----------------
__global__ void k_mkwl(int B, int N) {
    int t = threadIdx.x >> 5;     // one block, 1024 threads
    int lane = threadIdx.x & 31;
    if (t >= B * NC) return;
    int row = (t >> 3) * N + (t & 7);
    int beg = g_off[row], end = g_off[row + 1];
    int deg = end - beg;
    int pos = 0;
    if (lane == 0) pos = atomicAdd(&g_wlcount, deg + 1);
    pos = __shfl_sync(0xffffffffu, pos, 0);
    for (int i = lane; i < deg + 1; i += 32) {
        int idx = pos + i;
        if (idx < WLMAX)
            g_wl[idx] = (i == 0) ? row : g_csr[beg + i - 1];
    }
}

// ---------------- bf16x3 tensor-core multi-GEMM (no bias, direct store) ------
#define LDB 136

__device__ __forceinline__ void split_store4(float4 v, __nv_bfloat16* hi,
                                             __nv_bfloat16* lo, int idx) {
    __nv_bfloat16 h0 = __float2bfloat16(v.x), h1 = __float2bfloat16(v.y),
                  h2 = __float2bfloat16(v.z), h3 = __float2bfloat16(v.w);
    float l0 = v.x - __bfloat162float(h0), l1 = v.y - __bfloat162float(h1),
          l2 = v.z - __bfloat162float(h2), l3 = v.w - __bfloat162float(h3);
    __nv_bfloat162 hp0 = __halves2bfloat162(h0, h1), hp1 = __halves2bfloat162(h2, h3);
    uint2 hv; hv.x = *(unsigned*)&hp0; hv.y = *(unsigned*)&hp1;
    *(uint2*)&hi[idx] = hv;
    __nv_bfloat162 lp0 = __floats2bfloat162_rn(l0, l1), lp1 = __floats2bfloat162_rn(l2, l3);
    uint2 lv; lv.x = *(unsigned*)&lp0; lv.y = *(unsigned*)&lp1;
    *(uint2*)&lo[idx] = lv;
}

__global__ void k_gemmN(const float* __restrict__ A,
                        const float* __restrict__ W0, float* __restrict__ C0,
                        const float* __restrict__ W1, float* __restrict__ C1,
                        const float* __restrict__ W2, float* __restrict__ C2,
                        const float* __restrict__ W3, float* __restrict__ C3,
                        int M, int npass) {
    extern __shared__ char smraw[];
    __nv_bfloat16* Ahi = (__nv_bfloat16*)smraw;
    __nv_bfloat16* Alo = Ahi + 128 * LDB;
    __nv_bfloat16* Whi = Alo + 128 * LDB;
    __nv_bfloat16* Wlo = Whi + 128 * LDB;

    int tid = threadIdx.x;       // 256
    int row0 = blockIdx.x * 128;
    int r = tid >> 1, half = tid & 1;
    int cbase = half * 64;

    const float* Wt[4] = {W0, W1, W2, W3};
    float*       Ct[4] = {C0, C1, C2, C3};

    {
        int row = row0 + r;
        const float* ap = A + (size_t)row * D + cbase;
        #pragma unroll
        for (int q = 0; q < 16; q++) {
            float4 v = (row < M) ? *(const float4*)(ap + q * 4)
                                 : make_float4(0.f, 0.f, 0.f, 0.f);
            split_store4(v, Ahi, Alo, r * LDB + cbase + q * 4);
        }
    }

    int w  = tid >> 5;
    int wr = w >> 2, wc = w & 3;   // warp tile: 64 rows x 32 cols

    for (int pass = 0; pass < npass; pass++) {
        const float* W = Wt[pass];
        float* C       = Ct[pass];

        if (pass > 0) __syncthreads();
        {
            const float* wp = W + r * D + cbase;
            #pragma unroll
            for (int q = 0; q < 16; q++)
                split_store4(*(const float4*)(wp + q * 4), Whi, Wlo,
                             r * LDB + cbase + q * 4);
        }
        __syncthreads();

        wmma::fragment<wmma::accumulator, 16, 16, 16, float> acc[4][2];
        #pragma unroll
        for (int m = 0; m < 4; m++)
            #pragma unroll
            for (int n = 0; n < 2; n++) wmma::fill_fragment(acc[m][n], 0.f);

        wmma::fragment<wmma::matrix_a, 16, 16, 16, __nv_bfloat16, wmma::row_major> ah[4], al[4];
        wmma::fragment<wmma::matrix_b, 16, 16, 16, __nv_bfloat16, wmma::row_major> bh[2], bl[2];

        #pragma unroll
        for (int kk = 0; kk < 8; kk++) {
            int k0 = kk * 16;
            #pragma unroll
            for (int n = 0; n < 2; n++) {
                wmma::load_matrix_sync(bh[n], &Whi[k0 * LDB + wc * 32 + n * 16], LDB);
                wmma::load_matrix_sync(bl[n], &Wlo[k0 * LDB + wc * 32 + n * 16], LDB);
            }
            #pragma unroll
            for (int m = 0; m < 4; m++) {
                wmma::load_matrix_sync(ah[m], &Ahi[(wr * 64 + m * 16) * LDB + k0], LDB);
                wmma::load_matrix_sync(al[m], &Alo[(wr * 64 + m * 16) * LDB + k0], LDB);
            }
            #pragma unroll
            for (int m = 0; m < 4; m++)
                #pragma unroll
                for (int n = 0; n < 2; n++) {
                    wmma::mma_sync(acc[m][n], ah[m], bl[n], acc[m][n]);
                    wmma::mma_sync(acc[m][n], al[m], bh[n], acc[m][n]);
                    wmma::mma_sync(acc[m][n], ah[m], bh[n], acc[m][n]);
                }
        }

        #pragma unroll
        for (int m = 0; m < 4; m++)
            #pragma unroll
            for (int n = 0; n < 2; n++)
                wmma::store_matrix_sync(
                    C + (size_t)(row0 + wr * 64 + m * 16) * D + wc * 32 + n * 16,
                    acc[m][n], D, wmma::mem_row_major);
    }
}

// ---------------- GATv2 node body (bias-folded, prefetch) --------------------
__device__ __forceinline__ void gat_node(
    int w, int lane,
    const float* __restrict__ ul, const float* __restrict__ ur,
    const float* __restrict__ att, const float* __restrict__ bl,
    const float* __restrict__ br, const float* __restrict__ bo,
    float* __restrict__ out, float slope) {
    float4 bl4 = *(const float4*)(bl + lane * 4);
    float4 xr4 = *(const float4*)(ur + (size_t)w * D + lane * 4);
    {
        float4 br4 = *(const float4*)(br + lane * 4);
        xr4.x += bl4.x + br4.x; xr4.y += bl4.y + br4.y;
        xr4.z += bl4.z + br4.z; xr4.w += bl4.w + br4.w;
    }
    float4 at4 = *(const float4*)(att + lane * 4);
    int beg = g_off[w], end = g_off[w + 1];

    float m = -INFINITY, d = 0.f;
    float4 acc = make_float4(0.f, 0.f, 0.f, 0.f);

    float4 aCur = *(const float4*)(ul + (size_t)g_csr[beg] * D + lane * 4);
    int sNext = (beg + 1 < end) ? g_csr[beg + 1] : 0;

    for (int e = beg; e < end; e++) {
        float4 a = aCur;
        if (e + 1 < end) {
            aCur = *(const float4*)(ul + (size_t)sNext * D + lane * 4);
            if (e + 2 < end) sNext = g_csr[e + 2];
        }
        float t0 = a.x + xr4.x; t0 = (t0 > 0.f) ? t0 : 0.2f * t0;
        float t1 = a.y + xr4.y; t1 = (t1 > 0.f) ? t1 : 0.2f * t1;
        float t2 = a.z + xr4.z; t2 = (t2 > 0.f) ? t2 : 0.2f * t2;
        float t3 = a.w + xr4.w; t3 = (t3 > 0.f) ? t3 : 0.2f * t3;
        float p = t0 * at4.x + t1 * at4.y + t2 * at4.z + t3 * at4.w;
        #pragma unroll
        for (int o = 16; o; o >>= 1) p += __shfl_xor_sync(0xffffffffu, p, o);

        if (p <= m) {
            float wgt = __expf(p - m);
            d += wgt;
            acc.x += wgt * a.x; acc.y += wgt * a.y;
            acc.z += wgt * a.z; acc.w += wgt * a.w;
        } else {
            float c1 = __expf(m - p);
            d = d * c1 + 1.f;
            acc.x = acc.x * c1 + a.x; acc.y = acc.y * c1 + a.y;
            acc.z = acc.z * c1 + a.z; acc.w = acc.w * c1 + a.w;
            m = p;
        }
    }

    float inv = 1.f / (d + 1e-16f);
    float4 bo4 = *(const float4*)(bo + lane * 4);
    float o0 = acc.x * inv + bl4.x + bo4.x;
    float o1 = acc.y * inv + bl4.y + bo4.y;
    float o2 = acc.z * inv + bl4.z + bo4.z;
    float o3 = acc.w * inv + bl4.w + bo4.w;
    o0 = (o0 > 0.f) ? o0 : slope * o0;
    o1 = (o1 > 0.f) ? o1 : slope * o1;
    o2 = (o2 > 0.f) ? o2 : slope * o2;
    o3 = (o3 > 0.f) ? o3 : slope * o3;
    *(float4*)(out + (size_t)w * D + lane * 4) = make_float4(o0, o1, o2, o3);
}

__global__ void k_gat1(
    const float* __restrict__ ul, const float* __restrict__ ur,
    const float* __restrict__ att, const float* __restrict__ bl,
    const float* __restrict__ br, const float* __restrict__ bo,
    float* __restrict__ out, int w0, int wEnd, float slope) {
    int w = w0 + ((blockIdx.x * blockDim.x + threadIdx.x) >> 5);
    if (w >= wEnd) return;
    gat_node(w, threadIdx.x & 31, ul, ur, att, bl, br, bo, out, slope);
}

__global__ void k_gat1wl(
    const float* __restrict__ ul, const float* __restrict__ ur,
    const float* __restrict__ att, const float* __restrict__ bl,
    const float* __restrict__ br, const float* __restrict__ bo,
    float* __restrict__ out, float slope) {
    int idx = (blockIdx.x * blockDim.x + threadIdx.x) >> 5;
    int n = g_wlcount; if (n > WLMAX) n = WLMAX;
    if (idx >= n) return;
    gat_node(g_wl[idx], threadIdx.x & 31, ul, ur, att, bl, br, bo, out, slope);
}

// ---------------- c2 GATv2 + fused value head --------------------------------
__global__ void k_gatV(
    const float* __restrict__ ul, const float* __restrict__ ur,
    const float* __restrict__ att, const float* __restrict__ bl,
    const float* __restrict__ br, const float* __restrict__ bo,
    const float* __restrict__ fcW, const float* __restrict__ fcb,
    float* __restrict__ value, int M) {
    int w = (blockIdx.x * blockDim.x + threadIdx.x) >> 5;
    if (w >= M) return;
    int lane = threadIdx.x & 31;

    float4 bl4 = *(const float4*)(bl + lane * 4);
    float4 xr4 = *(const float4*)(ur + (size_t)w * D + lane * 4);
    {
        float4 br4 = *(const float4*)(br + lane * 4);
        xr4.x += bl4.x + br4.x; xr4.y += bl4.y + br4.y;
        xr4.z += bl4.z + br4.z; xr4.w += bl4.w + br4.w;
    }
    float4 at4 = *(const float4*)(att + lane * 4);
    int beg = g_off[w], end = g_off[w + 1];

    float m = -INFINITY, d = 0.f;
    float4 acc = make_float4(0.f, 0.f, 0.f, 0.f);

    float4 aCur = *(const float4*)(ul + (size_t)g_csr[beg] * D + lane * 4);
    int sNext = (beg + 1 < end) ? g_csr[beg + 1] : 0;

    for (int e = beg; e < end; e++) {
        float4 a = aCur;
        if (e + 1 < end) {
            aCur = *(const float4*)(ul + (size_t)sNext * D + lane * 4);
            if (e + 2 < end) sNext = g_csr[e + 2];
        }
        float t0 = a.x + xr4.x; t0 = (t0 > 0.f) ? t0 : 0.2f * t0;
        float t1 = a.y + xr4.y; t1 = (t1 > 0.f) ? t1 : 0.2f * t1;
        float t2 = a.z + xr4.z; t2 = (t2 > 0.f) ? t2 : 0.2f * t2;
        float t3 = a.w + xr4.w; t3 = (t3 > 0.f) ? t3 : 0.2f * t3;
        float p = t0 * at4.x + t1 * at4.y + t2 * at4.z + t3 * at4.w;
        #pragma unroll
        for (int o = 16; o; o >>= 1) p += __shfl_xor_sync(0xffffffffu, p, o);

        if (p <= m) {
            float wgt = __expf(p - m);
            d += wgt;
            acc.x += wgt * a.x; acc.y += wgt * a.y;
            acc.z += wgt * a.z; acc.w += wgt * a.w;
        } else {
            float c1 = __expf(m - p);
            d = d * c1 + 1.f;
            acc.x = acc.x * c1 + a.x; acc.y = acc.y * c1 + a.y;
            acc.z = acc.z * c1 + a.z; acc.w = acc.w * c1 + a.w;
            m = p;
        }
    }

    float inv = 1.f / (d + 1e-16f);
    float4 bo4 = *(const float4*)(bo + lane * 4);
    float4 fw = *(const float4*)(fcW + lane * 4);
    float v = (acc.x * inv + bl4.x + bo4.x) * fw.x
            + (acc.y * inv + bl4.y + bo4.y) * fw.y
            + (acc.z * inv + bl4.z + bo4.z) * fw.z
            + (acc.w * inv + bl4.w + bo4.w) * fw.w;
    #pragma unroll
    for (int o = 16; o; o >>= 1) v += __shfl_xor_sync(0xffffffffu, v, o);
    if (lane == 0) value[w] = v + fcb[0];
}

// ---------------- fused actor head: a2 projections + gat7 on 32 targets ------
__global__ void k_actorhead(const float* __restrict__ h,
                            const float* __restrict__ W1, const float* __restrict__ b1,
                            const float* __restrict__ W2, const float* __restrict__ b2,
                            const float* __restrict__ att, const float* __restrict__ bias,
                            float* __restrict__ lg, int B, int N) {
    __shared__ float W1s[D * CH], W2s[D * CH];
    int t = blockIdx.x;          // 0..B*NC-1
    int lane = threadIdx.x;      // 32 threads
    for (int i = lane; i < D * CH; i += 32) { W1s[i] = W1[i]; W2s[i] = W2[i]; }
    __syncwarp();

    int row = (t >> 3) * N + (t & 7);
    int k0 = lane * 4;

    float4 hr = *(const float4*)(h + (size_t)row * D + k0);
    float s2v[CH], attv[CH], b1v[CH];
    #pragma unroll
    for (int c = 0; c < CH; c++) {
        float p = hr.x * W2s[(k0 + 0) * CH + c] + hr.y * W2s[(k0 + 1) * CH + c]
                + hr.z * W2s[(k0 + 2) * CH + c] + hr.w * W2s[(k0 + 3) * CH + c];
        #pragma unroll
        for (int o = 16; o; o >>= 1) p += __shfl_xor_sync(0xffffffffu, p, o);
        s2v[c] = p + b2[c];
        attv[c] = att[c];
        b1v[c] = b1[c];
    }

    int beg = g_off[row], end = g_off[row + 1];
    float m = -INFINITY, d = 0.f;
    float acc[CH];
    #pragma unroll
    for (int c = 0; c < CH; c++) acc[c] = 0.f;

    for (int e = beg; e < end; e++) {
        int s = g_csr[e];
        float4 hs = *(const float4*)(h + (size_t)s * D + k0);
        float s1v[CH];
        #pragma unroll
        for (int c = 0; c < CH; c++) {
            float p = hs.x * W1s[(k0 + 0) * CH + c] + hs.y * W1s[(k0 + 1) * CH + c]
                    + hs.z * W1s[(k0 + 2) * CH + c] + hs.w * W1s[(k0 + 3) * CH + c];
            #pragma unroll
            for (int o = 16; o; o >>= 1) p += __shfl_xor_sync(0xffffffffu, p, o);
            s1v[c] = p + b1v[c];
        }
        float sc = 0.f;
        #pragma unroll
        for (int c = 0; c < CH; c++) {
            float tt = s1v[c] + s2v[c];
            tt = (tt > 0.f) ? tt : 0.2f * tt;
            sc = fmaf(tt, attv[c], sc);
        }
        if (sc <= m) {
            float wgt = __expf(sc - m);
            d += wgt;
            #pragma unroll
            for (int c = 0; c < CH; c++) acc[c] = fmaf(wgt, s1v[c], acc[c]);
        } else {
            float c1 = __expf(m - sc);
            d = d * c1 + 1.f;
            #pragma unroll
            for (int c = 0; c < CH; c++) acc[c] = acc[c] * c1 + s1v[c];
            m = sc;
        }
    }
    if (lane == 0) {
        float inv = 1.f / (d + 1e-16f);
        for (int c = 0; c < CH; c++)
            lg[t * CH + c] = acc[c] * inv + bias[c];
    }
}

// ---------------- actor head: softmax + gumbel + top-4 + sel -----------------
__global__ void k_actor(const float* __restrict__ logits, const float* __restrict__ gu,
                        float* __restrict__ out, int B, int N) {
    __shared__ float shp[4][NC][CH];
    int tid = threadIdx.x;            // 32 threads
    int b = tid >> 3, i = tid & 7;
    bool active = tid < B * NC;
    if (active) {
        float l[CH], mx = -INFINITY;
        for (int c = 0; c < CH; c++) { l[c] = logits[tid * CH + c]; mx = fmaxf(mx, l[c]); }
        float s = 0.f;
        for (int c = 0; c < CH; c++) { l[c] = expf(l[c] - mx); s += l[c]; }
        for (int c = 0; c < CH; c++) shp[b][i][c] = l[c] / s;
    }
    __syncthreads();
    if (active) {
        float sc[CH];
        for (int c = 0; c < CH; c++) {
            float u = gu[(b * NC + i) * CH + c];
            float g = -logf(-logf(u));
            sc[c] = logf(shp[b][i][c]) + g;
        }
        int base = (b * NC + i) * NS;
        int seloff = B * NC * NS;
        for (int j = 0; j < NS; j++) {
            int best = 0; float bv = -INFINITY;
            for (int c = 0; c < CH; c++)
                if (sc[c] > bv) { bv = sc[c]; best = c; }
            out[base + j] = (float)best;
            out[seloff + base + j] = shp[b][best][j];
            sc[best] = -INFINITY;
        }
    }
}

// ---------------- launch -----------------------------------------------------
extern "C" void kernel_launch(void* const* d_in, const int* in_sizes, int n_in,
                              void* d_out, int out_size) {
    const float* x  = (const float*)d_in[0];
    const int*   ei = (const int*)d_in[1];
    const float* gu = (const float*)d_in[2];
    const float* Wp[4][6];
    for (int l = 0; l < 4; l++)
        for (int j = 0; j < 6; j++)
            Wp[l][j] = (const float*)d_in[3 + l * 6 + j];
    const float* fcW = (const float*)d_in[27];
    const float* fcb = (const float*)d_in[28];

    int M = in_sizes[0] / D;
    int E = in_sizes[1] / 2;
    int B = in_sizes[2] / (NC * CH);
    int N = M / B;
    int ET = E + M;
    float* out = (float*)d_out;

    // one-time (first/correctness call, before graph capture) stream+event setup
    static cudaStream_t s1 = nullptr, s2 = nullptr, s3 = nullptr;
    static cudaEvent_t evA = nullptr, evB = nullptr, evG2 = nullptr,
                       evC0 = nullptr, evC1 = nullptr, evE = nullptr, evD = nullptr;
    if (!s1) {
        cudaStreamCreateWithFlags(&s1, cudaStreamNonBlocking);
        cudaStreamCreateWithFlags(&s2, cudaStreamNonBlocking);
        cudaStreamCreateWithFlags(&s3, cudaStreamNonBlocking);
        cudaEventCreateWithFlags(&evA, cudaEventDisableTiming);
        cudaEventCreateWithFlags(&evB, cudaEventDisableTiming);
        cudaEventCreateWithFlags(&evG2, cudaEventDisableTiming);
        cudaEventCreateWithFlags(&evC0, cudaEventDisableTiming);
        cudaEventCreateWithFlags(&evC1, cudaEventDisableTiming);
        cudaEventCreateWithFlags(&evE, cudaEventDisableTiming);
        cudaEventCreateWithFlags(&evD, cudaEventDisableTiming);
    }

    void *pc, *pwlc, *pxlA, *pxrA, *pxlC, *pxrC, *pyl, *pyr, *phA, *phC, *plg;
    cudaGetSymbolAddress(&pc,   g_count);
    cudaGetSymbolAddress(&pwlc, g_wlcount);
    cudaGetSymbolAddress(&pxlA, g_xlA);
    cudaGetSymbolAddress(&pxrA, g_xrA);
    cudaGetSymbolAddress(&pxlC, g_xlC);
    cudaGetSymbolAddress(&pxrC, g_xrC);
    cudaGetSymbolAddress(&pyl,  g_yl);
    cudaGetSymbolAddress(&pyr,  g_yr);
    cudaGetSymbolAddress(&phA,  g_hA);
    cudaGetSymbolAddress(&phC,  g_hC);
    cudaGetSymbolAddress(&plg,  g_lg);
    float* xlA = (float*)pxlA; float* xrA = (float*)pxrA;
    float* xlC = (float*)pxlC; float* xrC = (float*)pxrC;
    float* yl  = (float*)pyl;  float* yr  = (float*)pyr;
    float* hA  = (float*)phA;  float* hC  = (float*)phC;
    float* lg  = (float*)plg;

    const int tb = 256;
    size_t smemN = (size_t)4 * 128 * LDB * sizeof(__nv_bfloat16);  // 139264
    cudaFuncSetAttribute(k_gemmN, cudaFuncAttributeMaxDynamicSharedMemorySize, (int)smemN);
    int gg  = (M + 127) / 128;
    int gE  = (ET + tb - 1) / tb; if (gE > 4096) gE = 4096;
    int gws = (M * 32 + tb - 1) / tb;

    int Mh = (((M + 1) / 2 + 127) / 128) * 128;   // chunk split, 128-aligned
    if (Mh > M) Mh = M;
    int ggh0 = (Mh + 127) / 128;
    int ggh1 = (M - Mh + 127) / 128;
    int gw0  = (Mh * 32 + tb - 1) / tb;
    int gw1  = ((M - Mh) * 32 + tb - 1) / tb;
    int gwB  = (M * 32 + tb - 1) / tb;
    int gwl  = (WLMAX * 32 + tb - 1) / tb;

    // ---- fork: CSR build (s1) || critic layer-1 GEMM only (main) ----
    cudaEventRecord(evA, 0);
    cudaStreamWaitEvent(s1, evA, 0);

    cudaMemsetAsync(pc, 0, (size_t)(M + 1) * sizeof(int), s1);
    k_hist<<<gE, tb, 0, s1>>>(ei + E, E, M);
    k_scan<<<1, 1024, 0, s1>>>(M);
    k_scatter<<<gE, tb, 0, s1>>>(ei, ei + E, E, M);
    k_sortwarp<<<gws, tb, 0, s1>>>(M);
    cudaEventRecord(evB, s1);

    k_gemmN<<<gg, tb, smemN>>>(x, Wp[2][0], xlC, Wp[2][2], xrC,
                                  Wp[2][0], xlC, Wp[2][2], xrC, M, 2);
    cudaEventRecord(evG2, 0);

    // ---- actor branch (s3): actor GEMM (hidden under gatC) -> worklist ->
    //      pruned gat -> head ----
    cudaStreamWaitEvent(s3, evG2, 0);   // gemmC keeps full tensor throughput first
    k_gemmN<<<gg, tb, smemN, s3>>>(x, Wp[0][0], xlA, Wp[0][2], xrA,
                                      Wp[0][0], xlA, Wp[0][2], xrA, M, 2);
    cudaStreamWaitEvent(s3, evB, 0);
    cudaMemsetAsync(pwlc, 0, sizeof(int), s3);
    k_mkwl<<<1, 1024, 0, s3>>>(B, N);
    k_gat1wl<<<gwl, tb, 0, s3>>>(xlA, xrA, Wp[0][4], Wp[0][1], Wp[0][3], Wp[0][5],
                                 hA, 0.01f);
    k_actorhead<<<B * NC, 32, 0, s3>>>(hA, Wp[1][0], Wp[1][1], Wp[1][2], Wp[1][3],
                                       Wp[1][4], Wp[1][5], lg, B, N);
    k_actor<<<1, 32, 0, s3>>>(lg, gu, out, B, N);
    cudaEventRecord(evD, s3);

    // ---- critic: chunked gatC (main) pipelined with gemm2 (s2) ----
    cudaStreamWaitEvent(0, evB, 0);
    k_gat1<<<gw0, tb>>>(xlC, xrC, Wp[2][4], Wp[2][1], Wp[2][3], Wp[2][5],
                        hC, 0, Mh, 0.01f);
    cudaEventRecord(evC0, 0);
    if (M > Mh)
        k_gat1<<<gw1, tb>>>(xlC, xrC, Wp[2][4], Wp[2][1], Wp[2][3], Wp[2][5],
                            hC, Mh, M, 0.01f);
    cudaEventRecord(evC1, 0);

    cudaStreamWaitEvent(s2, evC0, 0);
    k_gemmN<<<ggh0, tb, smemN, s2>>>(hC, Wp[3][0], yl, Wp[3][2], yr,
                                         Wp[3][0], yl, Wp[3][2], yr, Mh, 2);
    cudaStreamWaitEvent(s2, evC1, 0);
    if (M > Mh)
        k_gemmN<<<ggh1, tb, smemN, s2>>>(hC + (size_t)Mh * D,
                                         Wp[3][0], yl + (size_t)Mh * D,
                                         Wp[3][2], yr + (size_t)Mh * D,
                                         Wp[3][0], yl + (size_t)Mh * D,
                                         Wp[3][2], yr + (size_t)Mh * D,
                                         M - Mh, 2);
    cudaEventRecord(evE, s2);

    // ---- gatV after full gemm2 ----
    cudaStreamWaitEvent(0, evE, 0);
    k_gatV<<<gwB, tb>>>(yl, yr, Wp[3][4], Wp[3][1], Wp[3][3], Wp[3][5],
                        fcW, fcb, out + 2 * B * NC * NS, M);

    // ---- final join ----
    cudaStreamWaitEvent(0, evD, 0);
}